// round 7
// baseline (speedup 1.0000x reference)
#include <cuda_runtime.h>
#include <cstdint>
#include <math.h>

// Problem constants (fixed by the reference)
#define NUM_K    1024      // primitives / codebook size
#define NUM_ROWS 32768     // 8 * 4096 tokens
#define DIM_D    1024      // embedding dim

#define TINY_F   1.17549435e-38f
#define LN2_F    0.693147180559945f
#define T_SMALL  4e-3f     // below this, MUFU relative error on t blows up -> exact path
#define CAND_EPS 3e-4f     // >3x proven |z_approx - z_exact| bound with margin
#define NEG_INF  __int_as_float(0xff800000)

// scratch: activation counts (zeroed via cudaMemsetAsync each launch)
__device__ int g_counts[NUM_K];

// ---------------------------------------------------------------------------
// Rotates. SHF path = 1 alu-pipe op. MUL path = IMAD.WIDE + IMAD.ADD, both
// fma-pipe: rotl(x,r) = lo(x*2^r) + hi(x*2^r)  (hi/lo bits disjoint -> '+'=='|',
// value-exact). Mixing them rebalances the alu/fma pipes (threefry's SHF+LOP3
// otherwise pile ~57 ops/elem on alu vs ~21 on fma).
// ---------------------------------------------------------------------------
__device__ __forceinline__ uint32_t tf_rotl(uint32_t x, int r) {
    return (x << r) | (x >> (32 - r));   // -> single SHF (alu pipe)
}

__device__ __forceinline__ uint32_t rotl_mul(uint32_t x, int r) {
    uint64_t p;
    asm("mul.wide.u32 %0, %1, %2;" : "=l"(p) : "r"(x), "r"(1u << r));
    return (uint32_t)p + (uint32_t)(p >> 32);   // IMAD.ADD-able (fma pipe)
}

// ---------------------------------------------------------------------------
// Threefry-2x32, 20 rounds, key = (0, 42) (jax.random.key(42)).
// Partitionable-mode 32-bit harvest: counter=(0, elem_idx); out = x0 ^ x1.
// Rotations alternate SHF/IMAD to balance pipes (10 each).
// ---------------------------------------------------------------------------
__device__ __forceinline__ uint32_t threefry_xor(uint32_t c1) {
    const uint32_t ks0 = 0u;
    const uint32_t ks1 = 42u;
    const uint32_t ks2 = 0x1BD11BDAu ^ 0u ^ 42u;
    uint32_t x0 = 0u + ks0;
    uint32_t x1 = c1 + ks1;
#define TF_RS(r) { x0 += x1; x1 = tf_rotl(x1, (r)); x1 ^= x0; }
#define TF_RM(r) { x0 += x1; x1 = rotl_mul(x1, (r)); x1 ^= x0; }
    TF_RS(13) TF_RM(15) TF_RS(26) TF_RM(6)
    x0 += ks1; x1 += ks2 + 1u;
    TF_RS(17) TF_RM(29) TF_RS(16) TF_RM(24)
    x0 += ks2; x1 += ks0 + 2u;
    TF_RS(13) TF_RM(15) TF_RS(26) TF_RM(6)
    x0 += ks0; x1 += ks1 + 3u;
    TF_RS(17) TF_RM(29) TF_RS(16) TF_RM(24)
    x0 += ks1; x1 += ks2 + 4u;
    TF_RS(13) TF_RM(15) TF_RS(26) TF_RM(6)
    x0 += ks2; x1 += ks0 + 5u;
#undef TF_RS
#undef TF_RM
    return x0 ^ x1;
}

// bits -> clamped uniform in [tiny,1): (bits>>9)|0x3f800000 bitcast, -1, clamp.
// bits>>9 done as hi(bits * 2^23) (IMAD.WIDE, fma pipe); OR == ADD since the
// mantissa (< 2^23) and 0x3f800000 are bit-disjoint. Value-exact.
__device__ __forceinline__ float uniform_from_bits(uint32_t bits) {
    uint64_t q;
    asm("mul.wide.u32 %0, %1, %2;" : "=l"(q) : "r"(bits), "r"(1u << 23));
    uint32_t mant = (uint32_t)(q >> 32);            // == bits >> 9
    float f = __uint_as_float(mant + 0x3f800000u) - 1.0f;
    return fmaxf(f, TINY_F);
}

// Exact gumbel: identical formula/precision to the reference (XLA lowers log ->
// libdevice logf = CUDA accurate logf). u must already be clamped.
__device__ __forceinline__ float gumbel_exact(float u) {
    return -logf(-logf(u));
}

// ---------------------------------------------------------------------------
// One block per row (structure proven in R3/R6).
// Phase 1: cheap MUFU-based z~ for all K (rare tiny-t elems take the exact
//          path inline, so their z~ carries zero error). Block max of z~.
// Phase 2: exact z (accurate logf) only for candidates within CAND_EPS of the
//          max; argmax over exact values (lower-index tie-break).
// Then gather primitives[idx] -> out, atomic count.
// ---------------------------------------------------------------------------
__global__ __launch_bounds__(256, 2)
void vybn_fused_kernel(const float* __restrict__ logits,
                       const float* __restrict__ prim,
                       float* __restrict__ out,
                       long long out_elems) {
    const int row  = blockIdx.x;
    const int t    = threadIdx.x;
    const int lane = t & 31;
    const int warp = t >> 5;

    // each thread handles k in [4t, 4t+4)
    const float4 lv = ((const float4*)(logits + (size_t)row * NUM_K))[t];
    const float lvi[4] = {lv.x, lv.y, lv.z, lv.w};
    const uint32_t base = (uint32_t)row * (uint32_t)NUM_K + (uint32_t)(4 * t);

    float u[4];   // clamped uniform, kept for the exact rescue path
    float za[4];  // z approx (exact for tiny-t elements)
    float zmax = NEG_INF;

    #pragma unroll
    for (int i = 0; i < 4; i++) {
        uint32_t bits = threefry_xor(base + (uint32_t)i);
        u[i] = uniform_from_bits(bits);
        // t~ = -ln(u) = log2(u) * (-ln2)   (MUFU.LG2 + FMUL)
        float tt = __log2f(u[i]) * (-LN2_F);
        float z;
        if (tt < T_SMALL) {
            // MUFU relative error too large here (u near 1) -> exact now,
            // so z~ carries zero error for these elements.
            z = lvi[i] + gumbel_exact(u[i]);
        } else {
            // g~ = -ln(t~); z~ = fma(log2(t~), -ln2, logit)
            z = fmaf(__log2f(tt), -LN2_F, lvi[i]);
        }
        za[i] = z;
        zmax = fmaxf(zmax, z);
    }

    // block max of z~ (values only)
    #pragma unroll
    for (int off = 16; off > 0; off >>= 1)
        zmax = fmaxf(zmax, __shfl_xor_sync(0xFFFFFFFFu, zmax, off));

    __shared__ float swv[8];
    __shared__ float swe[8];
    __shared__ int   swi[8];
    __shared__ int   s_idx;
    if (lane == 0) swv[warp] = zmax;
    __syncthreads();

    float gmax = swv[0];
    #pragma unroll
    for (int w = 1; w < 8; w++) gmax = fmaxf(gmax, swv[w]);
    const float thresh = gmax - CAND_EPS;

    // Phase 2: exact evaluation for candidates only
    float best = NEG_INF;
    int   bidx = 4 * t;
    #pragma unroll
    for (int i = 0; i < 4; i++) {
        if (za[i] >= thresh) {
            float ze = lvi[i] + gumbel_exact(u[i]);
            if (ze > best) { best = ze; bidx = 4 * t + i; }
        }
    }

    // warp argmax (ties -> lower index)
    #pragma unroll
    for (int off = 16; off > 0; off >>= 1) {
        float ov = __shfl_down_sync(0xFFFFFFFFu, best, off);
        int   oi = __shfl_down_sync(0xFFFFFFFFu, bidx, off);
        if (ov > best || (ov == best && oi < bidx)) { best = ov; bidx = oi; }
    }
    if (lane == 0) { swe[warp] = best; swi[warp] = bidx; }
    __syncthreads();

    if (t == 0) {
        best = swe[0]; bidx = swi[0];
        #pragma unroll
        for (int w = 1; w < 8; w++) {
            float ov = swe[w]; int oi = swi[w];
            if (ov > best || (ov == best && oi < bidx)) { best = ov; bidx = oi; }
        }
        s_idx = bidx;
        atomicAdd(&g_counts[bidx], 1);
        long long ioff = (long long)NUM_ROWS * DIM_D + row;
        if (ioff < out_elems) out[ioff] = (float)bidx;
    }
    __syncthreads();

    const int idx = s_idx;
    // embeddings row = primitives[idx] exactly (hard one-hot forward)
    float4 v = ((const float4*)(prim + (size_t)idx * DIM_D))[t];
    ((float4*)(out + (size_t)row * DIM_D))[t] = v;
}

__global__ void vybn_counts_kernel(float* __restrict__ out, long long out_elems) {
    int k = threadIdx.x + blockIdx.x * blockDim.x;
    if (k < NUM_K) {
        long long off = (long long)NUM_ROWS * DIM_D + NUM_ROWS + k;
        if (off < out_elems) out[off] = (float)g_counts[k];
    }
}

extern "C" void kernel_launch(void* const* d_in, const int* in_sizes, int n_in,
                              void* d_out, int out_size) {
    const float* logits = (const float*)d_in[0];
    const float* prim   = (const float*)d_in[1];
    if (n_in >= 2 && in_sizes[0] < in_sizes[1]) {
        const float* tmp = logits; logits = prim; prim = tmp;
    }
    float* out = (float*)d_out;

    void* cptr = nullptr;
    cudaGetSymbolAddress(&cptr, g_counts);
    cudaMemsetAsync(cptr, 0, sizeof(int) * NUM_K, 0);

    vybn_fused_kernel<<<NUM_ROWS, 256>>>(logits, prim, out, (long long)out_size);
    vybn_counts_kernel<<<1, NUM_K>>>(out, (long long)out_size);
}

// round 8
// speedup vs baseline: 1.1713x; 1.1713x over previous
#include <cuda_runtime.h>
#include <cstdint>
#include <math.h>

// Problem constants (fixed by the reference)
#define NUM_K    1024      // primitives / codebook size
#define NUM_ROWS 32768     // 8 * 4096 tokens
#define DIM_D    1024      // embedding dim

#define TINY_F   1.17549435e-38f
#define LN2_F    0.693147180559945f
#define T_SMALL  4e-3f     // below this, MUFU relative error on t blows up -> exact path
#define CAND_EPS 3e-4f     // >3x proven |z_approx - z_exact| bound with margin
#define NEG_INF  __int_as_float(0xff800000)

// ---------------------------------------------------------------------------
// Threefry-2x32, 20 rounds, key = (0, 42) (jax.random.key(42)).
// Partitionable-mode 32-bit harvest: counter=(0, elem_idx); out = x0 ^ x1.
// Pure SHF rotates (alu pipe) — proven fastest codegen (R6).
// ---------------------------------------------------------------------------
__device__ __forceinline__ uint32_t tf_rotl(uint32_t x, int r) {
    return (x << r) | (x >> (32 - r));
}

__device__ __forceinline__ uint32_t threefry_xor(uint32_t c1) {
    const uint32_t ks0 = 0u;
    const uint32_t ks1 = 42u;
    const uint32_t ks2 = 0x1BD11BDAu ^ 0u ^ 42u;
    uint32_t x0 = 0u + ks0;
    uint32_t x1 = c1 + ks1;
#define TF_R(r) { x0 += x1; x1 = tf_rotl(x1, (r)); x1 ^= x0; }
    TF_R(13) TF_R(15) TF_R(26) TF_R(6)
    x0 += ks1; x1 += ks2 + 1u;
    TF_R(17) TF_R(29) TF_R(16) TF_R(24)
    x0 += ks2; x1 += ks0 + 2u;
    TF_R(13) TF_R(15) TF_R(26) TF_R(6)
    x0 += ks0; x1 += ks1 + 3u;
    TF_R(17) TF_R(29) TF_R(16) TF_R(24)
    x0 += ks1; x1 += ks2 + 4u;
    TF_R(13) TF_R(15) TF_R(26) TF_R(6)
    x0 += ks2; x1 += ks0 + 5u;
#undef TF_R
    return x0 ^ x1;
}

// Exact gumbel: identical formula/precision to the reference (XLA lowers log ->
// libdevice logf = CUDA accurate logf). u must already be clamped.
__device__ __forceinline__ float gumbel_exact(float u) {
    return -logf(-logf(u));
}

// ---------------------------------------------------------------------------
// Tiny pre-kernel: zero the counts region of out (poisoned 0xAA by harness).
// Runs BEFORE the fused kernel each launch; fused kernel atomically adds into
// it. Launch order [zero, fused] also aligns ncu's "-s 5" onto the fused
// kernel (launch index 5 = fused).
// ---------------------------------------------------------------------------
__global__ void vybn_zero_counts(float* __restrict__ out, long long out_elems) {
    int k = threadIdx.x;
    long long off = (long long)NUM_ROWS * DIM_D + NUM_ROWS + k;
    if (off < out_elems) out[off] = 0.0f;
}

// ---------------------------------------------------------------------------
// One block per row (structure proven in R3/R6).
// Phase 1: cheap MUFU-based z~ for all K (rare tiny-t elems take the exact
//          path inline, so their z~ carries zero error). Block max of z~.
// Phase 2: exact z (accurate logf) only for candidates within CAND_EPS of the
//          max; argmax over exact values (lower-index tie-break).
// Then gather primitives[idx] -> out; counts via float atomicAdd into out.
// ---------------------------------------------------------------------------
__global__ __launch_bounds__(256, 2)
void vybn_fused_kernel(const float* __restrict__ logits,
                       const float* __restrict__ prim,
                       float* __restrict__ out,
                       long long out_elems) {
    const int row  = blockIdx.x;
    const int t    = threadIdx.x;
    const int lane = t & 31;
    const int warp = t >> 5;

    // each thread handles k in [4t, 4t+4)
    const float4 lv = ((const float4*)(logits + (size_t)row * NUM_K))[t];
    const float lvi[4] = {lv.x, lv.y, lv.z, lv.w};
    const uint32_t base = (uint32_t)row * (uint32_t)NUM_K + (uint32_t)(4 * t);

    float u[4];   // clamped uniform, kept for the exact rescue path
    float za[4];  // z approx (exact for tiny-t elements)
    float zmax = NEG_INF;

    #pragma unroll
    for (int i = 0; i < 4; i++) {
        uint32_t bits = threefry_xor(base + (uint32_t)i);
        float f = __uint_as_float((bits >> 9) | 0x3f800000u) - 1.0f;
        u[i] = fmaxf(f, TINY_F);
        // t~ = -ln(u) = log2(u) * (-ln2)   (MUFU.LG2 + FMUL)
        float tt = __log2f(u[i]) * (-LN2_F);
        float z;
        if (tt < T_SMALL) {
            // MUFU relative error too large here (u near 1) -> exact now,
            // so z~ carries zero error for these elements.
            z = lvi[i] + gumbel_exact(u[i]);
        } else {
            // g~ = -ln(t~); z~ = fma(log2(t~), -ln2, logit)
            z = fmaf(__log2f(tt), -LN2_F, lvi[i]);
        }
        za[i] = z;
        zmax = fmaxf(zmax, z);
    }

    // block max of z~ (values only)
    #pragma unroll
    for (int off = 16; off > 0; off >>= 1)
        zmax = fmaxf(zmax, __shfl_xor_sync(0xFFFFFFFFu, zmax, off));

    __shared__ float swv[8];
    __shared__ float swe[8];
    __shared__ int   swi[8];
    __shared__ int   s_idx;
    if (lane == 0) swv[warp] = zmax;
    __syncthreads();

    float gmax = swv[0];
    #pragma unroll
    for (int w = 1; w < 8; w++) gmax = fmaxf(gmax, swv[w]);
    const float thresh = gmax - CAND_EPS;

    // Phase 2: exact evaluation for candidates only
    float best = NEG_INF;
    int   bidx = 4 * t;
    #pragma unroll
    for (int i = 0; i < 4; i++) {
        if (za[i] >= thresh) {
            float ze = lvi[i] + gumbel_exact(u[i]);
            if (ze > best) { best = ze; bidx = 4 * t + i; }
        }
    }

    // warp argmax (ties -> lower index)
    #pragma unroll
    for (int off = 16; off > 0; off >>= 1) {
        float ov = __shfl_down_sync(0xFFFFFFFFu, best, off);
        int   oi = __shfl_down_sync(0xFFFFFFFFu, bidx, off);
        if (ov > best || (ov == best && oi < bidx)) { best = ov; bidx = oi; }
    }
    if (lane == 0) { swe[warp] = best; swi[warp] = bidx; }
    __syncthreads();

    if (t == 0) {
        best = swe[0]; bidx = swi[0];
        #pragma unroll
        for (int w = 1; w < 8; w++) {
            float ov = swe[w]; int oi = swi[w];
            if (ov > best || (ov == best && oi < bidx)) { best = ov; bidx = oi; }
        }
        s_idx = bidx;
        // counts: exact order-independent float accumulation (adds of 1.0f)
        long long coff = (long long)NUM_ROWS * DIM_D + NUM_ROWS + bidx;
        if (coff < out_elems) atomicAdd(&out[coff], 1.0f);
        long long ioff = (long long)NUM_ROWS * DIM_D + row;
        if (ioff < out_elems) out[ioff] = (float)bidx;
    }
    __syncthreads();

    const int idx = s_idx;
    // embeddings row = primitives[idx] exactly (hard one-hot forward)
    float4 v = ((const float4*)(prim + (size_t)idx * DIM_D))[t];
    ((float4*)(out + (size_t)row * DIM_D))[t] = v;
}

extern "C" void kernel_launch(void* const* d_in, const int* in_sizes, int n_in,
                              void* d_out, int out_size) {
    const float* logits = (const float*)d_in[0];
    const float* prim   = (const float*)d_in[1];
    if (n_in >= 2 && in_sizes[0] < in_sizes[1]) {
        const float* tmp = logits; logits = prim; prim = tmp;
    }
    float* out = (float*)d_out;

    vybn_zero_counts<<<1, NUM_K>>>(out, (long long)out_size);
    vybn_fused_kernel<<<NUM_ROWS, 256>>>(logits, prim, out, (long long)out_size);
}

// round 9
// speedup vs baseline: 1.2245x; 1.0454x over previous
#include <cuda_runtime.h>
#include <cstdint>
#include <math.h>

// Problem constants (fixed by the reference)
#define NUM_K    1024      // primitives / codebook size
#define NUM_ROWS 32768     // 8 * 4096 tokens
#define DIM_D    1024      // embedding dim

#define TINY_F   1.17549435e-38f
#define LN2_F    0.693147180559945f
#define T_SMALL  4e-3f     // clamp floor for MUFU-approx t; below -> force exact in phase 2
#define U_FORCE  0.99599f  // u > U_FORCE  <=>  t < ~4.017e-3 (covers tt<T_SMALL w/ margin)
#define CAND_EPS 3e-4f     // >3x proven |z_approx - z_exact| bound for unclamped elems
#define NEG_INF  __int_as_float(0xff800000)

// ---------------------------------------------------------------------------
// Threefry-2x32, 20 rounds, key = (0, 42) (jax.random.key(42)).
// Partitionable-mode 32-bit harvest: counter=(0, elem_idx); out = x0 ^ x1.
// Pure SHF rotates (proven fastest codegen).
// ---------------------------------------------------------------------------
__device__ __forceinline__ uint32_t tf_rotl(uint32_t x, int r) {
    return (x << r) | (x >> (32 - r));
}

__device__ __forceinline__ uint32_t threefry_xor(uint32_t c1) {
    const uint32_t ks0 = 0u;
    const uint32_t ks1 = 42u;
    const uint32_t ks2 = 0x1BD11BDAu ^ 0u ^ 42u;
    uint32_t x0 = 0u + ks0;
    uint32_t x1 = c1 + ks1;
#define TF_R(r) { x0 += x1; x1 = tf_rotl(x1, (r)); x1 ^= x0; }
    TF_R(13) TF_R(15) TF_R(26) TF_R(6)
    x0 += ks1; x1 += ks2 + 1u;
    TF_R(17) TF_R(29) TF_R(16) TF_R(24)
    x0 += ks2; x1 += ks0 + 2u;
    TF_R(13) TF_R(15) TF_R(26) TF_R(6)
    x0 += ks0; x1 += ks1 + 3u;
    TF_R(17) TF_R(29) TF_R(16) TF_R(24)
    x0 += ks1; x1 += ks2 + 4u;
    TF_R(13) TF_R(15) TF_R(26) TF_R(6)
    x0 += ks2; x1 += ks0 + 5u;
#undef TF_R
    return x0 ^ x1;
}

// Exact gumbel: identical formula/precision to the reference (XLA lowers log ->
// libdevice logf = CUDA accurate logf). u must already be clamped.
__device__ __forceinline__ float gumbel_exact(float u) {
    return -logf(-logf(u));
}

// ---------------------------------------------------------------------------
// Tiny pre-kernel: zero the counts region of out (poisoned 0xAA by harness).
// Launch order [zero, fused] keeps ncu "-s 5" on the fused kernel.
// ---------------------------------------------------------------------------
__global__ void vybn_zero_counts(float* __restrict__ out, long long out_elems) {
    int k = threadIdx.x;
    long long off = (long long)NUM_ROWS * DIM_D + NUM_ROWS + k;
    if (off < out_elems) out[off] = 0.0f;
}

// ---------------------------------------------------------------------------
// One block per row.
// Phase 1 (STRAIGHT-LINE, no branches): MUFU-based z~ with tt clamped at
//   T_SMALL. For u near 1 the clamp makes z~ a LOWER bound -> gmax is never
//   inflated -> screening stays sound. Block max of z~.
// Phase 2: candidates = (z~ >= gmax - CAND_EPS) OR (u > U_FORCE, i.e. the
//   clamped region where z~ underestimates). Exact z (accurate logf, inline)
//   only for candidates; argmax over exact values (lower-index tie-break).
// Then gather primitives[idx] -> out; counts via float atomicAdd into out.
// ---------------------------------------------------------------------------
__global__ __launch_bounds__(256, 2)
void vybn_fused_kernel(const float* __restrict__ logits,
                       const float* __restrict__ prim,
                       float* __restrict__ out,
                       long long out_elems) {
    const int row  = blockIdx.x;
    const int t    = threadIdx.x;
    const int lane = t & 31;
    const int warp = t >> 5;

    // each thread handles k in [4t, 4t+4)
    const float4 lv = ((const float4*)(logits + (size_t)row * NUM_K))[t];
    const float lvi[4] = {lv.x, lv.y, lv.z, lv.w};
    const uint32_t base = (uint32_t)row * (uint32_t)NUM_K + (uint32_t)(4 * t);

    float u[4];   // clamped uniform, kept for the exact rescue path
    float za[4];  // z approx (lower bound in the clamped region)
    float zmax = NEG_INF;

    #pragma unroll
    for (int i = 0; i < 4; i++) {
        uint32_t bits = threefry_xor(base + (uint32_t)i);
        float f = __uint_as_float((bits >> 9) | 0x3f800000u) - 1.0f;
        u[i] = fmaxf(f, TINY_F);
        // t~ = -ln(u) via MUFU.LG2 + FMUL; clamp so za error is bounded
        float tt  = __log2f(u[i]) * (-LN2_F);
        float ttc = fmaxf(tt, T_SMALL);
        za[i] = fmaf(__log2f(ttc), -LN2_F, lvi[i]);
        zmax = fmaxf(zmax, za[i]);
    }

    // block max of z~ (values only)
    #pragma unroll
    for (int off = 16; off > 0; off >>= 1)
        zmax = fmaxf(zmax, __shfl_xor_sync(0xFFFFFFFFu, zmax, off));

    __shared__ float swv[8];
    __shared__ float swe[8];
    __shared__ int   swi[8];
    __shared__ int   s_idx;
    if (lane == 0) swv[warp] = zmax;
    __syncthreads();

    float gmax = swv[0];
    #pragma unroll
    for (int w = 1; w < 8; w++) gmax = fmaxf(gmax, swv[w]);
    const float thresh = gmax - CAND_EPS;

    // Phase 2: exact evaluation for candidates only (inline logf; rare)
    float best = NEG_INF;
    int   bidx = 4 * t;
    #pragma unroll
    for (int i = 0; i < 4; i++) {
        if ((za[i] >= thresh) || (u[i] > U_FORCE)) {
            float ze = lvi[i] + gumbel_exact(u[i]);
            if (ze > best) { best = ze; bidx = 4 * t + i; }
        }
    }

    // warp argmax (ties -> lower index)
    #pragma unroll
    for (int off = 16; off > 0; off >>= 1) {
        float ov = __shfl_down_sync(0xFFFFFFFFu, best, off);
        int   oi = __shfl_down_sync(0xFFFFFFFFu, bidx, off);
        if (ov > best || (ov == best && oi < bidx)) { best = ov; bidx = oi; }
    }
    if (lane == 0) { swe[warp] = best; swi[warp] = bidx; }
    __syncthreads();

    if (t == 0) {
        best = swe[0]; bidx = swi[0];
        #pragma unroll
        for (int w = 1; w < 8; w++) {
            float ov = swe[w]; int oi = swi[w];
            if (ov > best || (ov == best && oi < bidx)) { best = ov; bidx = oi; }
        }
        s_idx = bidx;
        // counts: exact order-independent float accumulation (adds of 1.0f)
        long long coff = (long long)NUM_ROWS * DIM_D + NUM_ROWS + bidx;
        if (coff < out_elems) atomicAdd(&out[coff], 1.0f);
        long long ioff = (long long)NUM_ROWS * DIM_D + row;
        if (ioff < out_elems) out[ioff] = (float)bidx;
    }
    __syncthreads();

    const int idx = s_idx;
    // embeddings row = primitives[idx] exactly (hard one-hot forward)
    float4 v = ((const float4*)(prim + (size_t)idx * DIM_D))[t];
    ((float4*)(out + (size_t)row * DIM_D))[t] = v;
}

extern "C" void kernel_launch(void* const* d_in, const int* in_sizes, int n_in,
                              void* d_out, int out_size) {
    const float* logits = (const float*)d_in[0];
    const float* prim   = (const float*)d_in[1];
    if (n_in >= 2 && in_sizes[0] < in_sizes[1]) {
        const float* tmp = logits; logits = prim; prim = tmp;
    }
    float* out = (float*)d_out;

    vybn_zero_counts<<<1, NUM_K>>>(out, (long long)out_size);
    vybn_fused_kernel<<<NUM_ROWS, 256>>>(logits, prim, out, (long long)out_size);
}